// round 1
// baseline (speedup 1.0000x reference)
#include <cuda_runtime.h>

typedef unsigned long long u64;

#define M_TOK  16384
#define EMBED  1024
#define FFN    4096
#define NQ     8
#define BM     128
#define BN     128
#define BK     32

// Scratch (allocation-free rule: __device__ globals)
__device__ float g_q[M_TOK * NQ];        // 512 KB: q = cos(x[...,:8]) * cos(theta)
__device__ float g_W2T[FFN * EMBED];     // 16 MB: W2 transposed to [FFN][EMBED]

// ---------------- kernel 1: quantum layer ----------------
__global__ void qgen_kernel(const float* __restrict__ x, const float* __restrict__ theta) {
    int idx = blockIdx.x * blockDim.x + threadIdx.x;   // idx = m*NQ + i
    if (idx >= M_TOK * NQ) return;
    int i = idx & (NQ - 1);
    int m = idx >> 3;
    g_q[idx] = cosf(x[m * EMBED + i]) * cosf(theta[i]);
}

// ---------------- kernel 2: transpose W2 [EMBED][FFN] -> W2T [FFN][EMBED] ----------------
__global__ void transpose_kernel(const float* __restrict__ W2) {
    __shared__ float tile[32][33];
    int f0 = blockIdx.x * 32;    // along FFN
    int e0 = blockIdx.y * 32;    // along EMBED
    int tx = threadIdx.x, ty = threadIdx.y;
    #pragma unroll
    for (int j = ty; j < 32; j += 8)
        tile[j][tx] = W2[(e0 + j) * FFN + f0 + tx];   // tile[e_local][f_local]
    __syncthreads();
    #pragma unroll
    for (int j = ty; j < 32; j += 8)
        g_W2T[(f0 + j) * EMBED + e0 + tx] = tile[tx][j];
}

// ---------------- f32x2 helpers (FFMA2 path: 2x fp32 FMA throughput on sm_103a) ----------------
__device__ __forceinline__ u64 pack2(float a, float b) {
    u64 r;
    asm("mov.b64 %0, {%1, %2};" : "=l"(r) : "f"(a), "f"(b));
    return r;
}
__device__ __forceinline__ void unpack2(u64 p, float& a, float& b) {
    asm("mov.b64 {%0, %1}, %2;" : "=f"(a), "=f"(b) : "l"(p));
}
__device__ __forceinline__ u64 fma2(u64 a, u64 b, u64 c) {
    u64 d;
    asm("fma.rn.f32x2 %0, %1, %2, %3;" : "=l"(d) : "l"(a), "l"(b), "l"(c));
    return d;
}

// ---------------- kernel 3: fused  out = relu(q@W1^T + b1) @ W2^T + b2 ----------------
// Grid: (EMBED/BN=8, M_TOK/BM=128), 256 threads. Each thread: 8(m) x 8(n) tile,
// accumulators packed as f32x2 pairs along n. h tile regenerated in smem each BK step.
__global__ __launch_bounds__(256, 2)
void ffq_gemm(const float* __restrict__ W1, const float* __restrict__ b1,
              const float* __restrict__ b2, float* __restrict__ out)
{
    __shared__ float sH[BK][BM];        // h tile, [k][m]
    __shared__ float sW[BK][BN];        // W2T tile, [k][n]
    __shared__ float sW1[BK * NQ];
    __shared__ float sB1[BK];

    const int t   = threadIdx.x;
    const int tx  = t & 15;             // n-group
    const int ty  = t >> 4;             // m-group
    const int m0  = blockIdx.y * BM;
    const int n0  = blockIdx.x * BN;
    const int mh  = t & 127;            // h-gen: this thread's m row (fixed)
    const int kh0 = t >> 7;             // h-gen: k parity
    const int wk  = t >> 5;             // W2T staging: base k row (0..7)
    const int wc  = (t & 31) * 4;       // W2T staging: col

    // Per-thread q row for h-gen (coalesced, once)
    float qv[8];
    {
        const float4* qp = (const float4*)&g_q[(m0 + mh) * NQ];
        float4 q0 = qp[0], q1 = qp[1];
        qv[0]=q0.x; qv[1]=q0.y; qv[2]=q0.z; qv[3]=q0.w;
        qv[4]=q1.x; qv[5]=q1.y; qv[6]=q1.z; qv[7]=q1.w;
    }

    u64 acc[8][4];
    #pragma unroll
    for (int i = 0; i < 8; ++i)
        #pragma unroll
        for (int j = 0; j < 4; ++j) acc[i][j] = 0ull;

    for (int k0 = 0; k0 < FFN; k0 += BK) {
        // ---- prefetch next tiles into registers (overlaps barrier wait) ----
        float  w1v = W1[k0 * NQ + t];                    // 256 consecutive floats
        float  b1v = (t < BK) ? b1[k0 + t] : 0.0f;
        float4 wv[4];
        #pragma unroll
        for (int r = 0; r < 4; ++r)
            wv[r] = *(const float4*)&g_W2T[(k0 + wk + r * 8) * EMBED + n0 + wc];

        __syncthreads();   // previous iteration's smem reads complete

        sW1[t] = w1v;
        if (t < BK) sB1[t] = b1v;
        #pragma unroll
        for (int r = 0; r < 4; ++r)
            *(float4*)&sW[wk + r * 8][wc] = wv[r];

        __syncthreads();   // staged W1/b1 visible for h-gen

        // ---- h-gen: 16 cells per thread, m fixed = mh, k = kh0 + 2j ----
        #pragma unroll
        for (int j = 0; j < 16; ++j) {
            int k = kh0 + 2 * j;
            const float4* wp = (const float4*)&sW1[k * NQ];
            float4 w0 = wp[0], w1r = wp[1];
            float a = sB1[k];
            a = fmaf(qv[0], w0.x, a);  a = fmaf(qv[1], w0.y, a);
            a = fmaf(qv[2], w0.z, a);  a = fmaf(qv[3], w0.w, a);
            a = fmaf(qv[4], w1r.x, a); a = fmaf(qv[5], w1r.y, a);
            a = fmaf(qv[6], w1r.z, a); a = fmaf(qv[7], w1r.w, a);
            sH[k][mh] = fmaxf(a, 0.0f);
        }

        __syncthreads();   // h tile visible

        // ---- main loop: 64 FMA/thread/k as 32 FFMA2 ----
        #pragma unroll
        for (int k = 0; k < BK; ++k) {
            float4 a0 = *(const float4*)&sH[k][ty * 8];
            float4 a1 = *(const float4*)&sH[k][ty * 8 + 4];
            ulonglong2 bb0 = *(const ulonglong2*)&sW[k][tx * 4];        // n pairs 0..3
            ulonglong2 bb1 = *(const ulonglong2*)&sW[k][64 + tx * 4];   // n pairs 4..7
            float am[8] = {a0.x, a0.y, a0.z, a0.w, a1.x, a1.y, a1.z, a1.w};
            #pragma unroll
            for (int i = 0; i < 8; ++i) {
                u64 ap = pack2(am[i], am[i]);
                acc[i][0] = fma2(ap, bb0.x, acc[i][0]);
                acc[i][1] = fma2(ap, bb0.y, acc[i][1]);
                acc[i][2] = fma2(ap, bb1.x, acc[i][2]);
                acc[i][3] = fma2(ap, bb1.y, acc[i][3]);
            }
        }
    }

    // ---- epilogue: unpack, add b2, coalesced float4 stores ----
    float4 bv0 = *(const float4*)&b2[n0 + tx * 4];
    float4 bv1 = *(const float4*)&b2[n0 + 64 + tx * 4];
    #pragma unroll
    for (int i = 0; i < 8; ++i) {
        float v[8];
        unpack2(acc[i][0], v[0], v[1]);
        unpack2(acc[i][1], v[2], v[3]);
        unpack2(acc[i][2], v[4], v[5]);
        unpack2(acc[i][3], v[6], v[7]);
        float4 o0 = make_float4(v[0] + bv0.x, v[1] + bv0.y, v[2] + bv0.z, v[3] + bv0.w);
        float4 o1 = make_float4(v[4] + bv1.x, v[5] + bv1.y, v[6] + bv1.z, v[7] + bv1.w);
        int row = (m0 + ty * 8 + i) * EMBED;
        *(float4*)&out[row + n0 + tx * 4]      = o0;
        *(float4*)&out[row + n0 + 64 + tx * 4] = o1;
    }
}

extern "C" void kernel_launch(void* const* d_in, const int* in_sizes, int n_in,
                              void* d_out, int out_size) {
    const float* x     = (const float*)d_in[0];
    const float* theta = (const float*)d_in[1];
    const float* W1    = (const float*)d_in[2];
    const float* b1    = (const float*)d_in[3];
    const float* W2    = (const float*)d_in[4];
    const float* b2    = (const float*)d_in[5];
    float* out = (float*)d_out;

    qgen_kernel<<<(M_TOK * NQ + 255) / 256, 256>>>(x, theta);
    transpose_kernel<<<dim3(FFN / 32, EMBED / 32), dim3(32, 8)>>>(W2);
    ffq_gemm<<<dim3(EMBED / BN, M_TOK / BM), 256>>>(W1, b1, b2, out);
}

// round 6
// speedup vs baseline: 1.7425x; 1.7425x over previous
#include <cuda_runtime.h>
#include <cuda_bf16.h>
#include <cstdint>

#define M_TOK  16384
#define EMBED  1024
#define FFN    4096
#define NQ     8

#define TMT    128          // CTA M tile
#define TNT    128          // CTA N tile
#define BK     32           // K chunk
#define NCHUNK (FFN / BK)   // 128
#define NTHREADS 256        // 8 warps, each 64(M) x 32(N)

// ---- smem stage layout: A[128][hi64B|lo64B] swizzled, B same, W1 slice, b1 slice
#define A_OFF   0
#define B_OFF   16384
#define W1_OFF  32768
#define B1_OFF  33792
#define STAGE   34816
#define NSTAGE  3
#define SMEM_TOTAL (NSTAGE * STAGE)

// W2 split to bf16 hi/lo, layout [EMBED][FFN] (row n, K contiguous) = W2's own layout.
__device__ __nv_bfloat16 g_Bhi[EMBED * FFN];
__device__ __nv_bfloat16 g_Blo[EMBED * FFN];

// ---------------- helpers ----------------
__device__ __forceinline__ uint32_t smem_u32(const void* p) {
    uint32_t a;
    asm("{ .reg .u64 t; cvta.to.shared.u64 t, %1; cvt.u32.u64 %0, t; }" : "=r"(a) : "l"(p));
    return a;
}
__device__ __forceinline__ void cp_async16(uint32_t dst, const void* src) {
    asm volatile("cp.async.cg.shared.global [%0], [%1], 16;" :: "r"(dst), "l"(src) : "memory");
}
__device__ __forceinline__ void cp_commit() {
    asm volatile("cp.async.commit_group;" ::: "memory");
}
__device__ __forceinline__ void cp_wait1() {
    asm volatile("cp.async.wait_group 1;" ::: "memory");
}
__device__ __forceinline__ void sts128(uint32_t addr, uint32_t a, uint32_t b, uint32_t c, uint32_t d) {
    asm volatile("st.shared.v4.b32 [%0], {%1,%2,%3,%4};" :: "r"(addr), "r"(a), "r"(b), "r"(c), "r"(d) : "memory");
}
__device__ __forceinline__ void ldm_x4(uint32_t* r, uint32_t addr) {
    asm volatile("ldmatrix.sync.aligned.m8n8.x4.shared.b16 {%0,%1,%2,%3}, [%4];"
                 : "=r"(r[0]), "=r"(r[1]), "=r"(r[2]), "=r"(r[3]) : "r"(addr));
}
__device__ __forceinline__ void mma16816(float* d, const uint32_t* a, uint32_t b0, uint32_t b1) {
    asm volatile("mma.sync.aligned.m16n8k16.row.col.f32.bf16.bf16.f32 "
                 "{%0,%1,%2,%3}, {%4,%5,%6,%7}, {%8,%9}, {%0,%1,%2,%3};"
                 : "+f"(d[0]), "+f"(d[1]), "+f"(d[2]), "+f"(d[3])
                 : "r"(a[0]), "r"(a[1]), "r"(a[2]), "r"(a[3]), "r"(b0), "r"(b1));
}

// ---------------- prep: split W2 into bf16 hi/lo ----------------
__global__ void w2split_kernel(const float* __restrict__ W2) {
    int idx = blockIdx.x * blockDim.x + threadIdx.x;
    if (idx >= EMBED * FFN) return;
    float w = W2[idx];
    __nv_bfloat16 hi = __float2bfloat16_rn(w);
    g_Bhi[idx] = hi;
    g_Blo[idx] = __float2bfloat16_rn(w - __bfloat162float(hi));
}

// ---------------- main fused kernel ----------------
__global__ void __launch_bounds__(NTHREADS, 2)
ffq_hmma(const float* __restrict__ x, const float* __restrict__ theta,
         const float* __restrict__ W1, const float* __restrict__ b1,
         const float* __restrict__ b2, float* __restrict__ out)
{
    extern __shared__ __align__(1024) char smem[];
    const uint32_t sb = smem_u32(smem);
    const int tid  = threadIdx.x;
    const int wid  = tid >> 5;
    const int lane = tid & 31;
    const int m0   = blockIdx.y * TMT;
    const int n0   = blockIdx.x * TNT;

    // ---- warp MMA geometry ----
    const int mw = wid & 1;             // m-band (64)
    const int nw = wid >> 1;            // n-band (32)
    const int lr  = lane & 15;          // a-frag row
    const int lkh = lane >> 4;          // a-frag k-half
    const int lg  = lane >> 3;          // b-frag group
    const int l7  = lane & 7;

    // ---- h-gen geometry: thread owns m-row (tid&127), k-sub 16 ----
    const int mh = tid & 127;
    const int kb = (tid >> 7) * 16;     // 0 or 16

    // ---- B loader geometry: row tid&127, 4 chunk-units (hi if tid<128 else lo) ----
    const int brow = tid & 127;
    const int bcg  = (tid >> 7) * 4;

    // q row for h-gen (one-time)
    float qv[8];
    {
        float th[8];
        #pragma unroll
        for (int i = 0; i < 8; ++i) th[i] = cosf(theta[i]);
        const float4* xp = (const float4*)&x[(size_t)(m0 + mh) * EMBED];
        float4 x0 = xp[0], x1 = xp[1];
        qv[0] = cosf(x0.x) * th[0]; qv[1] = cosf(x0.y) * th[1];
        qv[2] = cosf(x0.z) * th[2]; qv[3] = cosf(x0.w) * th[3];
        qv[4] = cosf(x1.x) * th[4]; qv[5] = cosf(x1.y) * th[5];
        qv[6] = cosf(x1.z) * th[6]; qv[7] = cosf(x1.w) * th[7];
    }

    float acc[4][4][4];
    #pragma unroll
    for (int i = 0; i < 4; ++i)
        #pragma unroll
        for (int j = 0; j < 4; ++j)
            #pragma unroll
            for (int r = 0; r < 4; ++r) acc[i][j][r] = 0.0f;

    // ---------- stage loader (cp.async): B hi/lo + W1 slice + b1 slice ----------
    auto cp_stage = [&](int chunk, int st) {
        const int k0 = chunk * BK;
        const uint32_t base = sb + st * STAGE;
        // B: 4 x 16B per thread
        #pragma unroll
        for (int u = 0; u < 4; ++u) {
            int cu = bcg + u;                               // 0..7
            uint32_t d = base + B_OFF + ((uint32_t)brow * 128 + (uint32_t)((cu ^ (brow & 7)) * 16));
            const __nv_bfloat16* src = (bcg == 0)
                ? &g_Bhi[(size_t)(n0 + brow) * FFN + k0 + cu * 8]
                : &g_Blo[(size_t)(n0 + brow) * FFN + k0 + (cu - 4) * 8];
            cp_async16(d, src);
        }
        // W1 slice: rows k0..k0+31, 8 floats = 1KB
        if (tid < 64)
            cp_async16(base + W1_OFF + tid * 16, (const char*)W1 + (size_t)k0 * 32 + tid * 16);
        // b1 slice: 128B
        if (tid >= 64 && tid < 72)
            cp_async16(base + B1_OFF + (tid - 64) * 16, (const char*)b1 + (size_t)k0 * 4 + (tid - 64) * 16);
    };

    // ---------- h-gen: A tile (hi|lo bf16) from W1 slice in smem ----------
    auto hgen = [&](int st) {
        const uint32_t base = sb + st * STAGE;
        uint32_t hw[8], lw[8];
        #pragma unroll
        for (int p = 0; p < 8; ++p) {                       // pairs (kk=2p, 2p+1)
            float v2[2];
            #pragma unroll
            for (int e = 0; e < 2; ++e) {
                int kk = kb + 2 * p + e;
                const float4* wp = (const float4*)(smem + (st * STAGE + W1_OFF) + kk * 32);
                float4 w0 = wp[0], w1r = wp[1];
                float a = *(const float*)(smem + (st * STAGE + B1_OFF) + kk * 4);
                a = fmaf(qv[0], w0.x, a);  a = fmaf(qv[1], w0.y, a);
                a = fmaf(qv[2], w0.z, a);  a = fmaf(qv[3], w0.w, a);
                a = fmaf(qv[4], w1r.x, a); a = fmaf(qv[5], w1r.y, a);
                a = fmaf(qv[6], w1r.z, a); a = fmaf(qv[7], w1r.w, a);
                v2[e] = fmaxf(a, 0.0f);
            }
            __nv_bfloat162 hp = __float22bfloat162_rn(make_float2(v2[0], v2[1]));
            float2 hf = __bfloat1622float2(hp);
            __nv_bfloat162 lp = __float22bfloat162_rn(make_float2(v2[0] - hf.x, v2[1] - hf.y));
            hw[p] = *(uint32_t*)&hp;
            lw[p] = *(uint32_t*)&lp;
        }
        const int x7 = mh & 7;
        const int c0 = kb >> 3;                             // 0 or 2
        uint32_t rb = base + A_OFF + (uint32_t)mh * 128;
        sts128(rb + (uint32_t)(((c0 + 0) ^ x7) * 16), hw[0], hw[1], hw[2], hw[3]);
        sts128(rb + (uint32_t)(((c0 + 1) ^ x7) * 16), hw[4], hw[5], hw[6], hw[7]);
        sts128(rb + (uint32_t)(((c0 + 4) ^ x7) * 16), lw[0], lw[1], lw[2], lw[3]);
        sts128(rb + (uint32_t)(((c0 + 5) ^ x7) * 16), lw[4], lw[5], lw[6], lw[7]);
    };

    // ---------- MMA on one stage: 3-term hi/lo ----------
    const int xa = lr & 7;
    auto do_mma = [&](int st) {
        const uint32_t Ab = sb + st * STAGE + A_OFF;
        const uint32_t Bb = sb + st * STAGE + B_OFF;
        #pragma unroll
        for (int ks = 0; ks < 2; ++ks) {
            uint32_t ah[4][4], al[4][4], bh[2][4], bl[2][4];
            // A rows for ldmatrix: m = mw*64 + i*16 + lr
            #pragma unroll
            for (int i = 0; i < 4; ++i) {
                uint32_t row = (uint32_t)(mw * 64 + i * 16 + lr) * 128;
                ldm_x4(ah[i], Ab + row + (uint32_t)(((2 * ks + lkh) ^ xa) * 16));
            }
            // B hi: two ldmatrix.x4, each covers 2 n-tiles
            #pragma unroll
            for (int p = 0; p < 2; ++p) {
                uint32_t row = (uint32_t)(nw * 32 + (2 * p + (lg >> 1)) * 8 + l7) * 128;
                ldm_x4(bh[p], Bb + row + (uint32_t)(((2 * ks + (lg & 1)) ^ l7) * 16));
            }
            #pragma unroll
            for (int i = 0; i < 4; ++i)
                #pragma unroll
                for (int j = 0; j < 4; ++j)
                    mma16816(acc[i][j], ah[i], bh[j >> 1][2 * (j & 1)], bh[j >> 1][2 * (j & 1) + 1]);
            // B lo
            #pragma unroll
            for (int p = 0; p < 2; ++p) {
                uint32_t row = (uint32_t)(nw * 32 + (2 * p + (lg >> 1)) * 8 + l7) * 128;
                ldm_x4(bl[p], Bb + row + (uint32_t)(((2 * ks + (lg & 1) + 4) ^ l7) * 16));
            }
            #pragma unroll
            for (int i = 0; i < 4; ++i)
                #pragma unroll
                for (int j = 0; j < 4; ++j)
                    mma16816(acc[i][j], ah[i], bl[j >> 1][2 * (j & 1)], bl[j >> 1][2 * (j & 1) + 1]);
            // A lo x B hi
            #pragma unroll
            for (int i = 0; i < 4; ++i) {
                uint32_t row = (uint32_t)(mw * 64 + i * 16 + lr) * 128;
                ldm_x4(al[i], Ab + row + (uint32_t)(((2 * ks + lkh + 4) ^ xa) * 16));
            }
            #pragma unroll
            for (int i = 0; i < 4; ++i)
                #pragma unroll
                for (int j = 0; j < 4; ++j)
                    mma16816(acc[i][j], al[i], bh[j >> 1][2 * (j & 1)], bh[j >> 1][2 * (j & 1) + 1]);
        }
    };

    // ---------- pipeline ----------
    cp_stage(0, 0); cp_commit();
    cp_stage(1, 1); cp_commit();
    cp_wait1();                 // stage0 complete
    __syncthreads();
    hgen(0);
    __syncthreads();

    for (int c = 0; c < NCHUNK; ++c) {
        const int st = c % 3;
        do_mma(st);
        __syncthreads();
        if (c + 2 < NCHUNK) cp_stage(c + 2, (c + 2) % 3);
        cp_commit();
        cp_wait1();             // stage (c+1)%3 data complete
        if (c + 1 < NCHUNK) hgen((c + 1) % 3);
        __syncthreads();
    }

    // ---------- epilogue: add b2, direct stores ----------
    const int rw = lane >> 2;
    const int cw = 2 * (lane & 3);
    #pragma unroll
    for (int j = 0; j < 4; ++j) {
        int colg = n0 + nw * 32 + j * 8 + cw;
        float2 bv = *(const float2*)&b2[colg];
        #pragma unroll
        for (int i = 0; i < 4; ++i) {
            int rowg = m0 + mw * 64 + i * 16 + rw;
            float2 o0 = make_float2(acc[i][j][0] + bv.x, acc[i][j][1] + bv.y);
            float2 o1 = make_float2(acc[i][j][2] + bv.x, acc[i][j][3] + bv.y);
            *(float2*)&out[(size_t)rowg * EMBED + colg] = o0;
            *(float2*)&out[(size_t)(rowg + 8) * EMBED + colg] = o1;
        }
    }
}

extern "C" void kernel_launch(void* const* d_in, const int* in_sizes, int n_in,
                              void* d_out, int out_size) {
    const float* x     = (const float*)d_in[0];
    const float* theta = (const float*)d_in[1];
    const float* W1    = (const float*)d_in[2];
    const float* b1    = (const float*)d_in[3];
    const float* W2    = (const float*)d_in[4];
    const float* b2    = (const float*)d_in[5];
    float* out = (float*)d_out;

    cudaFuncSetAttribute(ffq_hmma, cudaFuncAttributeMaxDynamicSharedMemorySize, SMEM_TOTAL);

    w2split_kernel<<<(EMBED * FFN + 255) / 256, 256>>>(W2);
    ffq_hmma<<<dim3(EMBED / TNT, M_TOK / TMT), NTHREADS, SMEM_TOTAL>>>(x, theta, W1, b1, b2, out);
}

// round 11
// speedup vs baseline: 2.6629x; 1.5283x over previous
#include <cuda_runtime.h>
#include <cuda_bf16.h>
#include <cstdint>

#define M_TOK  16384
#define EMBED  1024
#define FFN    4096
#define NQ     8

#define TMT    128
#define TNT    128
#define BK     32
#define NCHUNK (FFN / BK)      // 128
#define NMTILE (M_TOK / TMT)   // 128
#define NNTILE (EMBED / TNT)   // 8
#define NTHREADS 256

// smem stage: A tile 16KB + B tile 16KB
#define A_OFF  0
#define B_OFF  16384
#define STAGE  32768
#define NSTAGE 3
#define SMEM_TOTAL (NSTAGE * STAGE)

// Pre-tiled operands, byte layout identical to the smem stage tiles:
// block(t, c) = 128 rows x 128B, row = [hi 4x16B | lo 4x16B], unit u swizzled by (u ^ (row&7)).
__device__ float g_q[M_TOK * NQ];
__device__ char  g_A[(size_t)NMTILE * NCHUNK * 16384];   // 268 MB
__device__ char  g_B[(size_t)NNTILE * NCHUNK * 16384];   // 16 MB

// ---------------- helpers ----------------
__device__ __forceinline__ uint32_t smem_u32(const void* p) {
    uint32_t a;
    asm("{ .reg .u64 t; cvta.to.shared.u64 t, %1; cvt.u32.u64 %0, t; }" : "=r"(a) : "l"(p));
    return a;
}
__device__ __forceinline__ void cp_async16(uint32_t dst, const void* src) {
    asm volatile("cp.async.cg.shared.global [%0], [%1], 16;" :: "r"(dst), "l"(src) : "memory");
}
__device__ __forceinline__ void cp_commit() {
    asm volatile("cp.async.commit_group;" ::: "memory");
}
__device__ __forceinline__ void cp_wait1() {
    asm volatile("cp.async.wait_group 1;" ::: "memory");
}
__device__ __forceinline__ void ldm_x4(uint32_t* r, uint32_t addr) {
    asm volatile("ldmatrix.sync.aligned.m8n8.x4.shared.b16 {%0,%1,%2,%3}, [%4];"
                 : "=r"(r[0]), "=r"(r[1]), "=r"(r[2]), "=r"(r[3]) : "r"(addr));
}
__device__ __forceinline__ void mma16816(float* d, const uint32_t* a, uint32_t b0, uint32_t b1) {
    asm volatile("mma.sync.aligned.m16n8k16.row.col.f32.bf16.bf16.f32 "
                 "{%0,%1,%2,%3}, {%4,%5,%6,%7}, {%8,%9}, {%0,%1,%2,%3};"
                 : "+f"(d[0]), "+f"(d[1]), "+f"(d[2]), "+f"(d[3])
                 : "r"(a[0]), "r"(a[1]), "r"(a[2]), "r"(a[3]), "r"(b0), "r"(b1));
}
__device__ __forceinline__ void split2(float v0, float v1, uint32_t& h, uint32_t& l) {
    __nv_bfloat162 hp = __float22bfloat162_rn(make_float2(v0, v1));
    float2 hf = __bfloat1622float2(hp);
    __nv_bfloat162 lp = __float22bfloat162_rn(make_float2(v0 - hf.x, v1 - hf.y));
    h = *(uint32_t*)&hp;
    l = *(uint32_t*)&lp;
}

// ---------------- prep 1: q = cos(x[..., :8]) * cos(theta) ----------------
__global__ void qgen_kernel(const float* __restrict__ x, const float* __restrict__ theta) {
    int idx = blockIdx.x * blockDim.x + threadIdx.x;
    if (idx >= M_TOK * NQ) return;
    int i = idx & (NQ - 1);
    int m = idx >> 3;
    g_q[idx] = cosf(x[(size_t)m * EMBED + i]) * cosf(theta[i]);
}

// ---------------- prep 2: A blocks = hi/lo bf16 of relu(q@W1^T + b1), tiled+swizzled ----------------
__global__ void __launch_bounds__(256) a_gen(const float* __restrict__ W1, const float* __restrict__ b1) {
    __shared__ float sW1[BK * NQ];
    __shared__ float sB1[BK];
    __shared__ char  tile[16384];
    const int t = threadIdx.x;
    const int chunk = blockIdx.x, mtile = blockIdx.y;
    const int k0 = chunk * BK, m0 = mtile * TMT;

    if (t < 64) ((float4*)sW1)[t] = ((const float4*)(W1 + (size_t)k0 * NQ))[t];
    if (t >= 64 && t < 64 + BK) sB1[t - 64] = b1[k0 + (t - 64)];
    __syncthreads();

    const int row = t >> 1;
    const int kb  = (t & 1) * 16;
    const float4* qp = (const float4*)&g_q[(size_t)(m0 + row) * NQ];
    float4 q0 = qp[0], q1 = qp[1];
    float qv[8] = {q0.x, q0.y, q0.z, q0.w, q1.x, q1.y, q1.z, q1.w};

    uint32_t hw[8], lw[8];
    #pragma unroll
    for (int p = 0; p < 8; ++p) {
        float v2[2];
        #pragma unroll
        for (int e = 0; e < 2; ++e) {
            int kk = kb + 2 * p + e;
            float4 w0 = ((const float4*)sW1)[kk * 2];
            float4 w1r = ((const float4*)sW1)[kk * 2 + 1];
            float a = sB1[kk];
            a = fmaf(qv[0], w0.x, a);  a = fmaf(qv[1], w0.y, a);
            a = fmaf(qv[2], w0.z, a);  a = fmaf(qv[3], w0.w, a);
            a = fmaf(qv[4], w1r.x, a); a = fmaf(qv[5], w1r.y, a);
            a = fmaf(qv[6], w1r.z, a); a = fmaf(qv[7], w1r.w, a);
            v2[e] = fmaxf(a, 0.0f);
        }
        split2(v2[0], v2[1], hw[p], lw[p]);
    }
    const int x7 = row & 7;
    const int c0 = kb >> 3;                         // 0 or 2
    const uint32_t rb = (uint32_t)row * 128;
    *(uint4*)&tile[rb + (uint32_t)(((c0 + 0) ^ x7) * 16)] = make_uint4(hw[0], hw[1], hw[2], hw[3]);
    *(uint4*)&tile[rb + (uint32_t)(((c0 + 1) ^ x7) * 16)] = make_uint4(hw[4], hw[5], hw[6], hw[7]);
    *(uint4*)&tile[rb + (uint32_t)(((c0 + 4) ^ x7) * 16)] = make_uint4(lw[0], lw[1], lw[2], lw[3]);
    *(uint4*)&tile[rb + (uint32_t)(((c0 + 5) ^ x7) * 16)] = make_uint4(lw[4], lw[5], lw[6], lw[7]);
    __syncthreads();

    uint4* dst = (uint4*)(g_A + ((size_t)(mtile * NCHUNK + chunk)) * 16384);
    const uint4* srcp = (const uint4*)tile;
    #pragma unroll
    for (int i = 0; i < 4; ++i) dst[t + i * 256] = srcp[t + i * 256];
}

// ---------------- prep 3: B blocks = hi/lo bf16 of W2, tiled+swizzled ----------------
__global__ void __launch_bounds__(256) b_gen(const float* __restrict__ W2) {
    __shared__ char tile[16384];
    const int t = threadIdx.x;
    const int chunk = blockIdx.x, ntile = blockIdx.y;
    const int k0 = chunk * BK, n0 = ntile * TNT;
    const int row = t >> 1;
    const int kb  = (t & 1) * 16;

    const float4* src = (const float4*)&W2[(size_t)(n0 + row) * FFN + k0 + kb];
    float v[16];
    #pragma unroll
    for (int i = 0; i < 4; ++i) {
        float4 f = src[i];
        v[4 * i] = f.x; v[4 * i + 1] = f.y; v[4 * i + 2] = f.z; v[4 * i + 3] = f.w;
    }
    uint32_t hw[8], lw[8];
    #pragma unroll
    for (int j = 0; j < 8; ++j) split2(v[2 * j], v[2 * j + 1], hw[j], lw[j]);

    const int x7 = row & 7;
    const int c0 = kb >> 3;
    const uint32_t rb = (uint32_t)row * 128;
    *(uint4*)&tile[rb + (uint32_t)(((c0 + 0) ^ x7) * 16)] = make_uint4(hw[0], hw[1], hw[2], hw[3]);
    *(uint4*)&tile[rb + (uint32_t)(((c0 + 1) ^ x7) * 16)] = make_uint4(hw[4], hw[5], hw[6], hw[7]);
    *(uint4*)&tile[rb + (uint32_t)(((c0 + 4) ^ x7) * 16)] = make_uint4(lw[0], lw[1], lw[2], lw[3]);
    *(uint4*)&tile[rb + (uint32_t)(((c0 + 5) ^ x7) * 16)] = make_uint4(lw[4], lw[5], lw[6], lw[7]);
    __syncthreads();

    uint4* dst = (uint4*)(g_B + ((size_t)(ntile * NCHUNK + chunk)) * 16384);
    const uint4* srcp = (const uint4*)tile;
    #pragma unroll
    for (int i = 0; i < 4; ++i) dst[t + i * 256] = srcp[t + i * 256];
}

// ---------------- main GEMM: out = A@B^T + b2 (3-term hi/lo bf16) ----------------
__global__ void __launch_bounds__(NTHREADS, 2)
ffq_mm(const float* __restrict__ b2, float* __restrict__ out)
{
    extern __shared__ __align__(1024) char smem[];
    const uint32_t sb = smem_u32(smem);
    const int tid  = threadIdx.x;
    const int wid  = tid >> 5;
    const int lane = tid & 31;
    const int m0   = blockIdx.y * TMT;
    const int n0   = blockIdx.x * TNT;

    const char* gA = g_A + ((size_t)blockIdx.y * NCHUNK) * 16384;
    const char* gB = g_B + ((size_t)blockIdx.x * NCHUNK) * 16384;

    // warp MMA geometry (proven in round 6)
    const int mw  = wid & 1;
    const int nw  = wid >> 1;
    const int lr  = lane & 15;
    const int lkh = lane >> 4;
    const int lg  = lane >> 3;
    const int l7  = lane & 7;
    const int xa  = lr & 7;

    float acc[4][4][4];
    #pragma unroll
    for (int i = 0; i < 4; ++i)
        #pragma unroll
        for (int j = 0; j < 4; ++j)
            #pragma unroll
            for (int r = 0; r < 4; ++r) acc[i][j][r] = 0.0f;

    auto cp_stage = [&](int chunk, int st) {
        const uint32_t base = sb + st * STAGE;
        const char* sa = gA + (size_t)chunk * 16384;
        const char* sbg = gB + (size_t)chunk * 16384;
        #pragma unroll
        for (int i = 0; i < 4; ++i)
            cp_async16(base + A_OFF + (uint32_t)(tid + i * 256) * 16, sa + (size_t)(tid + i * 256) * 16);
        #pragma unroll
        for (int i = 0; i < 4; ++i)
            cp_async16(base + B_OFF + (uint32_t)(tid + i * 256) * 16, sbg + (size_t)(tid + i * 256) * 16);
    };

    auto do_mma = [&](int st) {
        const uint32_t Ab = sb + st * STAGE + A_OFF;
        const uint32_t Bb = sb + st * STAGE + B_OFF;
        #pragma unroll
        for (int ks = 0; ks < 2; ++ks) {
            uint32_t ah[4][4], al[4][4], bh[2][4], bl[2][4];
            #pragma unroll
            for (int i = 0; i < 4; ++i) {
                uint32_t row = (uint32_t)(mw * 64 + i * 16 + lr) * 128;
                ldm_x4(ah[i], Ab + row + (uint32_t)(((2 * ks + lkh) ^ xa) * 16));
            }
            #pragma unroll
            for (int p = 0; p < 2; ++p) {
                uint32_t row = (uint32_t)(nw * 32 + (2 * p + (lg >> 1)) * 8 + l7) * 128;
                ldm_x4(bh[p], Bb + row + (uint32_t)(((2 * ks + (lg & 1)) ^ l7) * 16));
            }
            #pragma unroll
            for (int i = 0; i < 4; ++i)
                #pragma unroll
                for (int j = 0; j < 4; ++j)
                    mma16816(acc[i][j], ah[i], bh[j >> 1][2 * (j & 1)], bh[j >> 1][2 * (j & 1) + 1]);
            #pragma unroll
            for (int p = 0; p < 2; ++p) {
                uint32_t row = (uint32_t)(nw * 32 + (2 * p + (lg >> 1)) * 8 + l7) * 128;
                ldm_x4(bl[p], Bb + row + (uint32_t)(((2 * ks + (lg & 1) + 4) ^ l7) * 16));
            }
            #pragma unroll
            for (int i = 0; i < 4; ++i)
                #pragma unroll
                for (int j = 0; j < 4; ++j)
                    mma16816(acc[i][j], ah[i], bl[j >> 1][2 * (j & 1)], bl[j >> 1][2 * (j & 1) + 1]);
            #pragma unroll
            for (int i = 0; i < 4; ++i) {
                uint32_t row = (uint32_t)(mw * 64 + i * 16 + lr) * 128;
                ldm_x4(al[i], Ab + row + (uint32_t)(((2 * ks + lkh + 4) ^ xa) * 16));
            }
            #pragma unroll
            for (int i = 0; i < 4; ++i)
                #pragma unroll
                for (int j = 0; j < 4; ++j)
                    mma16816(acc[i][j], al[i], bh[j >> 1][2 * (j & 1)], bh[j >> 1][2 * (j & 1) + 1]);
        }
    };

    // ---- pipeline: one barrier per chunk ----
    cp_stage(0, 0); cp_commit();
    cp_stage(1, 1); cp_commit();
    cp_wait1();                 // chunk 0 resident
    __syncthreads();

    for (int c = 0; c < NCHUNK; ++c) {
        const int st = c % 3;
        if (c + 2 < NCHUNK) cp_stage(c + 2, (c + 2) % 3);
        cp_commit();
        do_mma(st);
        cp_wait1();             // chunk c+1 resident
        __syncthreads();
    }

    // ---- epilogue ----
    const int rw = lane >> 2;
    const int cw = 2 * (lane & 3);
    #pragma unroll
    for (int j = 0; j < 4; ++j) {
        int colg = n0 + nw * 32 + j * 8 + cw;
        float2 bv = *(const float2*)&b2[colg];
        #pragma unroll
        for (int i = 0; i < 4; ++i) {
            int rowg = m0 + mw * 64 + i * 16 + rw;
            float2 o0 = make_float2(acc[i][j][0] + bv.x, acc[i][j][1] + bv.y);
            float2 o1 = make_float2(acc[i][j][2] + bv.x, acc[i][j][3] + bv.y);
            *(float2*)&out[(size_t)rowg * EMBED + colg] = o0;
            *(float2*)&out[(size_t)(rowg + 8) * EMBED + colg] = o1;
        }
    }
}

extern "C" void kernel_launch(void* const* d_in, const int* in_sizes, int n_in,
                              void* d_out, int out_size) {
    const float* x     = (const float*)d_in[0];
    const float* theta = (const float*)d_in[1];
    const float* W1    = (const float*)d_in[2];
    const float* b1    = (const float*)d_in[3];
    const float* W2    = (const float*)d_in[4];
    const float* b2    = (const float*)d_in[5];
    float* out = (float*)d_out;

    cudaFuncSetAttribute(ffq_mm, cudaFuncAttributeMaxDynamicSharedMemorySize, SMEM_TOTAL);

    qgen_kernel<<<(M_TOK * NQ + 255) / 256, 256>>>(x, theta);
    a_gen<<<dim3(NCHUNK, NMTILE), 256>>>(W1, b1);
    b_gen<<<dim3(NCHUNK, NNTILE), 256>>>(W2);
    ffq_mm<<<dim3(NNTILE, NMTILE), 256, SMEM_TOTAL>>>(b2, out);
}

// round 12
// speedup vs baseline: 2.8153x; 1.0572x over previous
#include <cuda_runtime.h>
#include <cuda_bf16.h>
#include <cstdint>

#define M_TOK  16384
#define EMBED  1024
#define FFN    4096
#define NQ     8

#define TMT    128
#define BK     32
#define NCHUNK (FFN / BK)      // 128
#define NMTILE (M_TOK / TMT)   // 128
#define NNTILE (EMBED / 128)   // 8
#define NTHREADS 256

#define FULL_MT   111                       // mtiles 0..110 as full 128x128 tiles
#define NFULL     (FULL_MT * NNTILE)        // 888 = 3 full waves at 2 CTA/SM
#define NHALF     ((NMTILE - FULL_MT) * 16) // 272 half tiles (128x64)
#define GRID_MM   (NFULL + NHALF)           // 1160

// smem stage: A tile 16KB + B tile 16KB (half path uses first 8KB of B)
#define A_OFF  0
#define B_OFF  16384
#define STAGE  32768
#define NSTAGE 3
#define SMEM_TOTAL (NSTAGE * STAGE)

// Pre-tiled operands, byte layout identical to the smem stage tiles:
// block(t, c) = 128 rows x 128B, row = [hi 4x16B | lo 4x16B], unit u swizzled by (u ^ (row&7)).
__device__ char g_A[(size_t)NMTILE * NCHUNK * 16384];   // 268 MB
__device__ char g_B[(size_t)NNTILE * NCHUNK * 16384];   // 16 MB

// ---------------- helpers ----------------
__device__ __forceinline__ uint32_t smem_u32(const void* p) {
    uint32_t a;
    asm("{ .reg .u64 t; cvta.to.shared.u64 t, %1; cvt.u32.u64 %0, t; }" : "=r"(a) : "l"(p));
    return a;
}
__device__ __forceinline__ void cp_async16(uint32_t dst, const void* src) {
    asm volatile("cp.async.cg.shared.global [%0], [%1], 16;" :: "r"(dst), "l"(src) : "memory");
}
__device__ __forceinline__ void cp_commit() {
    asm volatile("cp.async.commit_group;" ::: "memory");
}
__device__ __forceinline__ void cp_wait1() {
    asm volatile("cp.async.wait_group 1;" ::: "memory");
}
__device__ __forceinline__ void cp_wait0() {
    asm volatile("cp.async.wait_group 0;" ::: "memory");
}
__device__ __forceinline__ void ldm_x4(uint32_t* r, uint32_t addr) {
    asm volatile("ldmatrix.sync.aligned.m8n8.x4.shared.b16 {%0,%1,%2,%3}, [%4];"
                 : "=r"(r[0]), "=r"(r[1]), "=r"(r[2]), "=r"(r[3]) : "r"(addr));
}
__device__ __forceinline__ void mma16816(float* d, const uint32_t* a, uint32_t b0, uint32_t b1) {
    asm volatile("mma.sync.aligned.m16n8k16.row.col.f32.bf16.bf16.f32 "
                 "{%0,%1,%2,%3}, {%4,%5,%6,%7}, {%8,%9}, {%0,%1,%2,%3};"
                 : "+f"(d[0]), "+f"(d[1]), "+f"(d[2]), "+f"(d[3])
                 : "r"(a[0]), "r"(a[1]), "r"(a[2]), "r"(a[3]), "r"(b0), "r"(b1));
}
__device__ __forceinline__ void split2(float v0, float v1, uint32_t& h, uint32_t& l) {
    __nv_bfloat162 hp = __float22bfloat162_rn(make_float2(v0, v1));
    float2 hf = __bfloat1622float2(hp);
    __nv_bfloat162 lp = __float22bfloat162_rn(make_float2(v0 - hf.x, v1 - hf.y));
    h = *(uint32_t*)&hp;
    l = *(uint32_t*)&lp;
}

// ---------------- prep 1: A blocks = hi/lo bf16 of relu(q@W1^T + b1) (q fused) ----------------
__global__ void __launch_bounds__(256) a_gen(const float* __restrict__ x, const float* __restrict__ theta,
                                             const float* __restrict__ W1, const float* __restrict__ b1) {
    __shared__ float sW1[BK * NQ];
    __shared__ float sB1[BK];
    __shared__ char  tile[16384];
    const int t = threadIdx.x;
    const int chunk = blockIdx.x, mtile = blockIdx.y;
    const int k0 = chunk * BK, m0 = mtile * TMT;

    if (t < 64) ((float4*)sW1)[t] = ((const float4*)(W1 + (size_t)k0 * NQ))[t];
    if (t >= 64 && t < 64 + BK) sB1[t - 64] = b1[k0 + (t - 64)];
    __syncthreads();

    const int row = t >> 1;
    const int kb  = (t & 1) * 16;
    float qv[8];
    {
        const float4* xp = (const float4*)&x[(size_t)(m0 + row) * EMBED];
        float4 x0 = xp[0], x1 = xp[1];
        qv[0] = cosf(x0.x) * cosf(theta[0]); qv[1] = cosf(x0.y) * cosf(theta[1]);
        qv[2] = cosf(x0.z) * cosf(theta[2]); qv[3] = cosf(x0.w) * cosf(theta[3]);
        qv[4] = cosf(x1.x) * cosf(theta[4]); qv[5] = cosf(x1.y) * cosf(theta[5]);
        qv[6] = cosf(x1.z) * cosf(theta[6]); qv[7] = cosf(x1.w) * cosf(theta[7]);
    }

    uint32_t hw[8], lw[8];
    #pragma unroll
    for (int p = 0; p < 8; ++p) {
        float v2[2];
        #pragma unroll
        for (int e = 0; e < 2; ++e) {
            int kk = kb + 2 * p + e;
            float4 w0 = ((const float4*)sW1)[kk * 2];
            float4 w1r = ((const float4*)sW1)[kk * 2 + 1];
            float a = sB1[kk];
            a = fmaf(qv[0], w0.x, a);  a = fmaf(qv[1], w0.y, a);
            a = fmaf(qv[2], w0.z, a);  a = fmaf(qv[3], w0.w, a);
            a = fmaf(qv[4], w1r.x, a); a = fmaf(qv[5], w1r.y, a);
            a = fmaf(qv[6], w1r.z, a); a = fmaf(qv[7], w1r.w, a);
            v2[e] = fmaxf(a, 0.0f);
        }
        split2(v2[0], v2[1], hw[p], lw[p]);
    }
    const int x7 = row & 7;
    const int c0 = kb >> 3;
    const uint32_t rb = (uint32_t)row * 128;
    *(uint4*)&tile[rb + (uint32_t)(((c0 + 0) ^ x7) * 16)] = make_uint4(hw[0], hw[1], hw[2], hw[3]);
    *(uint4*)&tile[rb + (uint32_t)(((c0 + 1) ^ x7) * 16)] = make_uint4(hw[4], hw[5], hw[6], hw[7]);
    *(uint4*)&tile[rb + (uint32_t)(((c0 + 4) ^ x7) * 16)] = make_uint4(lw[0], lw[1], lw[2], lw[3]);
    *(uint4*)&tile[rb + (uint32_t)(((c0 + 5) ^ x7) * 16)] = make_uint4(lw[4], lw[5], lw[6], lw[7]);
    __syncthreads();

    uint4* dst = (uint4*)(g_A + ((size_t)(mtile * NCHUNK + chunk)) * 16384);
    const uint4* srcp = (const uint4*)tile;
    #pragma unroll
    for (int i = 0; i < 4; ++i) dst[t + i * 256] = srcp[t + i * 256];
}

// ---------------- prep 2: B blocks = hi/lo bf16 of W2, tiled+swizzled ----------------
__global__ void __launch_bounds__(256) b_gen(const float* __restrict__ W2) {
    __shared__ char tile[16384];
    const int t = threadIdx.x;
    const int chunk = blockIdx.x, ntile = blockIdx.y;
    const int k0 = chunk * BK, n0 = ntile * 128;
    const int row = t >> 1;
    const int kb  = (t & 1) * 16;

    const float4* src = (const float4*)&W2[(size_t)(n0 + row) * FFN + k0 + kb];
    float v[16];
    #pragma unroll
    for (int i = 0; i < 4; ++i) {
        float4 f = src[i];
        v[4 * i] = f.x; v[4 * i + 1] = f.y; v[4 * i + 2] = f.z; v[4 * i + 3] = f.w;
    }
    uint32_t hw[8], lw[8];
    #pragma unroll
    for (int j = 0; j < 8; ++j) split2(v[2 * j], v[2 * j + 1], hw[j], lw[j]);

    const int x7 = row & 7;
    const int c0 = kb >> 3;
    const uint32_t rb = (uint32_t)row * 128;
    *(uint4*)&tile[rb + (uint32_t)(((c0 + 0) ^ x7) * 16)] = make_uint4(hw[0], hw[1], hw[2], hw[3]);
    *(uint4*)&tile[rb + (uint32_t)(((c0 + 1) ^ x7) * 16)] = make_uint4(hw[4], hw[5], hw[6], hw[7]);
    *(uint4*)&tile[rb + (uint32_t)(((c0 + 4) ^ x7) * 16)] = make_uint4(lw[0], lw[1], lw[2], lw[3]);
    *(uint4*)&tile[rb + (uint32_t)(((c0 + 5) ^ x7) * 16)] = make_uint4(lw[4], lw[5], lw[6], lw[7]);
    __syncthreads();

    uint4* dst = (uint4*)(g_B + ((size_t)(ntile * NCHUNK + chunk)) * 16384);
    const uint4* srcp = (const uint4*)tile;
    #pragma unroll
    for (int i = 0; i < 4; ++i) dst[t + i * 256] = srcp[t + i * 256];
}

// ---------------- GEMM path, templated on tile width ----------------
// HALF=false: 128x128 tile (warp 64x32). HALF=true: 128x64 tile (warp 64x16).
template<bool HALF>
__device__ __forceinline__ void gemm_path(
    uint32_t sb, const char* __restrict__ gA, const char* __restrict__ gB,
    int m0, int n0, const float* __restrict__ b2, float* __restrict__ out, int tid)
{
    constexpr int NJ = HALF ? 2 : 4;     // n j-tiles per warp
    constexpr int NP = HALF ? 1 : 2;     // B ldmatrix groups
    constexpr int NBU = HALF ? 2 : 4;    // B cp units per thread (x256x16B)

    const int wid  = tid >> 5;
    const int lane = tid & 31;
    const int mw  = wid & 1;
    const int nw  = wid >> 1;            // 0..3
    const int lr  = lane & 15;
    const int lkh = lane >> 4;
    const int lg  = lane >> 3;
    const int l7  = lane & 7;
    const int xa  = lr & 7;

    float acc[4][NJ][4];
    #pragma unroll
    for (int i = 0; i < 4; ++i)
        #pragma unroll
        for (int j = 0; j < NJ; ++j)
            #pragma unroll
            for (int r = 0; r < 4; ++r) acc[i][j][r] = 0.0f;

    auto cp_stage = [&](int chunk, uint32_t base) {
        const char* sa  = gA + (size_t)chunk * 16384;
        const char* sbg = gB + (size_t)chunk * 16384;
        #pragma unroll
        for (int i = 0; i < 4; ++i)
            cp_async16(base + A_OFF + (uint32_t)(tid + i * 256) * 16, sa + (size_t)(tid + i * 256) * 16);
        #pragma unroll
        for (int i = 0; i < NBU; ++i)
            cp_async16(base + B_OFF + (uint32_t)(tid + i * 256) * 16, sbg + (size_t)(tid + i * 256) * 16);
    };

    auto do_mma = [&](uint32_t base) {
        const uint32_t Ab = base + A_OFF;
        const uint32_t Bb = base + B_OFF;
        #pragma unroll
        for (int ks = 0; ks < 2; ++ks) {
            uint32_t ah[4][4], al[4][4], bh[NP][4], bl[NP][4];
            #pragma unroll
            for (int i = 0; i < 4; ++i) {
                uint32_t row = (uint32_t)(mw * 64 + i * 16 + lr) * 128;
                ldm_x4(ah[i], Ab + row + (uint32_t)(((2 * ks + lkh) ^ xa) * 16));
            }
            #pragma unroll
            for (int p = 0; p < NP; ++p) {
                uint32_t row = HALF
                    ? (uint32_t)(nw * 16 + (lg >> 1) * 8 + l7) * 128
                    : (uint32_t)(nw * 32 + (2 * p + (lg >> 1)) * 8 + l7) * 128;
                ldm_x4(bh[p], Bb + row + (uint32_t)(((2 * ks + (lg & 1)) ^ l7) * 16));
            }
            #pragma unroll
            for (int i = 0; i < 4; ++i)
                #pragma unroll
                for (int j = 0; j < NJ; ++j)
                    mma16816(acc[i][j], ah[i], bh[j >> 1][2 * (j & 1)], bh[j >> 1][2 * (j & 1) + 1]);
            #pragma unroll
            for (int p = 0; p < NP; ++p) {
                uint32_t row = HALF
                    ? (uint32_t)(nw * 16 + (lg >> 1) * 8 + l7) * 128
                    : (uint32_t)(nw * 32 + (2 * p + (lg >> 1)) * 8 + l7) * 128;
                ldm_x4(bl[p], Bb + row + (uint32_t)(((2 * ks + (lg & 1) + 4) ^ l7) * 16));
            }
            #pragma unroll
            for (int i = 0; i < 4; ++i)
                #pragma unroll
                for (int j = 0; j < NJ; ++j)
                    mma16816(acc[i][j], ah[i], bl[j >> 1][2 * (j & 1)], bl[j >> 1][2 * (j & 1) + 1]);
            #pragma unroll
            for (int i = 0; i < 4; ++i) {
                uint32_t row = (uint32_t)(mw * 64 + i * 16 + lr) * 128;
                ldm_x4(al[i], Ab + row + (uint32_t)(((2 * ks + lkh + 4) ^ xa) * 16));
            }
            #pragma unroll
            for (int i = 0; i < 4; ++i)
                #pragma unroll
                for (int j = 0; j < NJ; ++j)
                    mma16816(acc[i][j], al[i], bh[j >> 1][2 * (j & 1)], bh[j >> 1][2 * (j & 1) + 1]);
        }
    };

    // ---- pipeline: 3 stages, chunk loop unrolled x3 so stages are compile-time ----
    cp_stage(0, sb + 0 * STAGE); cp_commit();
    cp_stage(1, sb + 1 * STAGE); cp_commit();
    cp_wait1();
    __syncthreads();

    for (int cb = 0; cb < NCHUNK - 2; cb += 3) {
        #pragma unroll
        for (int j = 0; j < 3; ++j) {
            cp_stage(cb + j + 2, sb + ((j + 2) % 3) * STAGE);
            cp_commit();
            do_mma(sb + j * STAGE);
            cp_wait1();
            __syncthreads();
        }
    }
    // chunks 126 (stage 0) and 127 (stage 1)
    do_mma(sb + 0 * STAGE);
    cp_wait0();
    __syncthreads();
    do_mma(sb + 1 * STAGE);

    // ---- epilogue ----
    const int rw = lane >> 2;
    const int cw = 2 * (lane & 3);
    #pragma unroll
    for (int j = 0; j < NJ; ++j) {
        int colg = n0 + nw * (HALF ? 16 : 32) + j * 8 + cw;
        float2 bv = *(const float2*)&b2[colg];
        #pragma unroll
        for (int i = 0; i < 4; ++i) {
            int rowg = m0 + mw * 64 + i * 16 + rw;
            float2 o0 = make_float2(acc[i][j][0] + bv.x, acc[i][j][1] + bv.y);
            float2 o1 = make_float2(acc[i][j][2] + bv.x, acc[i][j][3] + bv.y);
            *(float2*)&out[(size_t)rowg * EMBED + colg] = o0;
            *(float2*)&out[(size_t)(rowg + 8) * EMBED + colg] = o1;
        }
    }
}

// ---------------- main GEMM kernel: 888 full tiles + 272 half tiles ----------------
__global__ void __launch_bounds__(NTHREADS, 2)
ffq_mm(const float* __restrict__ b2, float* __restrict__ out)
{
    extern __shared__ __align__(1024) char smem[];
    const uint32_t sb = smem_u32(smem);
    const int tid = threadIdx.x;
    const int flat = blockIdx.x;

    if (flat < NFULL) {
        const int mtile = flat >> 3;
        const int n0 = (flat & 7) * 128;
        const char* gA = g_A + (size_t)mtile * NCHUNK * 16384;
        const char* gB = g_B + (size_t)(n0 >> 7) * NCHUNK * 16384;
        gemm_path<false>(sb, gA, gB, mtile * TMT, n0, b2, out, tid);
    } else {
        const int r = flat - NFULL;
        const int mtile = FULL_MT + (r >> 4);
        const int nh = r & 15;
        const int n0 = nh * 64;
        const char* gA = g_A + (size_t)mtile * NCHUNK * 16384;
        const char* gB = g_B + (size_t)(nh >> 1) * NCHUNK * 16384 + (size_t)(nh & 1) * 64 * 128;
        gemm_path<true>(sb, gA, gB, mtile * TMT, n0, b2, out, tid);
    }
}

extern "C" void kernel_launch(void* const* d_in, const int* in_sizes, int n_in,
                              void* d_out, int out_size) {
    const float* x     = (const float*)d_in[0];
    const float* theta = (const float*)d_in[1];
    const float* W1    = (const float*)d_in[2];
    const float* b1    = (const float*)d_in[3];
    const float* W2    = (const float*)d_in[4];
    const float* b2    = (const float*)d_in[5];
    float* out = (float*)d_out;

    cudaFuncSetAttribute(ffq_mm, cudaFuncAttributeMaxDynamicSharedMemorySize, SMEM_TOTAL);

    a_gen<<<dim3(NCHUNK, NMTILE), 256>>>(x, theta, W1, b1);
    b_gen<<<dim3(NCHUNK, NNTILE), 256>>>(W2);
    ffq_mm<<<GRID_MM, NTHREADS, SMEM_TOTAL>>>(b2, out);
}

// round 14
// speedup vs baseline: 2.8931x; 1.0276x over previous
#include <cuda_runtime.h>
#include <cuda_bf16.h>
#include <cstdint>

#define M_TOK  16384
#define EMBED  1024
#define FFN    4096
#define NQ     8

#define TMT    128
#define BK     32
#define NCHUNK (FFN / BK)      // 128
#define NMTILE (M_TOK / TMT)   // 128
#define NNTILE (EMBED / 128)   // 8
#define NTHREADS 256

#define FULL_MT   111                       // mtiles 0..110 as full 128x128 tiles
#define NFULL     (FULL_MT * NNTILE)        // 888 = 3 full waves at 2 CTA/SM
#define NHALF     ((NMTILE - FULL_MT) * 16) // 272 half tiles (128x64)
#define GRID_MM   (NFULL + NHALF)           // 1160

// smem stage: A tile 16KB + B tile 16KB (half path uses first 8KB of B)
#define A_OFF  0
#define B_OFF  16384
#define STAGE  32768
#define NSTAGE 3
#define SMEM_TOTAL (NSTAGE * STAGE)

// Pre-tiled operands, byte layout identical to the smem stage tiles:
// block(t, c) = 128 rows x 128B, row = [hi 4x16B | lo 4x16B], unit u swizzled by (u ^ (row&7)).
__device__ char g_A[(size_t)NMTILE * NCHUNK * 16384];   // 268 MB
__device__ char g_B[(size_t)NNTILE * NCHUNK * 16384];   // 16 MB

// ---------------- helpers ----------------
__device__ __forceinline__ uint32_t smem_u32(const void* p) {
    uint32_t a;
    asm("{ .reg .u64 t; cvta.to.shared.u64 t, %1; cvt.u32.u64 %0, t; }" : "=r"(a) : "l"(p));
    return a;
}
__device__ __forceinline__ void cp_async16(uint32_t dst, const void* src) {
    asm volatile("cp.async.cg.shared.global [%0], [%1], 16;" :: "r"(dst), "l"(src) : "memory");
}
__device__ __forceinline__ void cp_commit() {
    asm volatile("cp.async.commit_group;" ::: "memory");
}
__device__ __forceinline__ void cp_wait1() {
    asm volatile("cp.async.wait_group 1;" ::: "memory");
}
__device__ __forceinline__ void cp_wait0() {
    asm volatile("cp.async.wait_group 0;" ::: "memory");
}
__device__ __forceinline__ void ldm_x4(uint32_t* r, uint32_t addr) {
    asm volatile("ldmatrix.sync.aligned.m8n8.x4.shared.b16 {%0,%1,%2,%3}, [%4];"
                 : "=r"(r[0]), "=r"(r[1]), "=r"(r[2]), "=r"(r[3]) : "r"(addr));
}
__device__ __forceinline__ void mma16816(float* d, const uint32_t* a, uint32_t b0, uint32_t b1) {
    asm volatile("mma.sync.aligned.m16n8k16.row.col.f32.bf16.bf16.f32 "
                 "{%0,%1,%2,%3}, {%4,%5,%6,%7}, {%8,%9}, {%0,%1,%2,%3};"
                 : "+f"(d[0]), "+f"(d[1]), "+f"(d[2]), "+f"(d[3])
                 : "r"(a[0]), "r"(a[1]), "r"(a[2]), "r"(a[3]), "r"(b0), "r"(b1));
}
__device__ __forceinline__ void split2(float v0, float v1, uint32_t& h, uint32_t& l) {
    __nv_bfloat162 hp = __float22bfloat162_rn(make_float2(v0, v1));
    float2 hf = __bfloat1622float2(hp);
    __nv_bfloat162 lp = __float22bfloat162_rn(make_float2(v0 - hf.x, v1 - hf.y));
    h = *(uint32_t*)&hp;
    l = *(uint32_t*)&lp;
}

// ---------------- prep 1: A blocks, amortized over 16 chunks, direct STG ----------------
// grid: (8 chunk-groups, 128 mtiles). Thread: row = t>>1 (fixed), kb = (t&1)*16.
__global__ void __launch_bounds__(256) a_gen(const float* __restrict__ x, const float* __restrict__ theta,
                                             const float* __restrict__ W1, const float* __restrict__ b1) {
    __shared__ float sW1[16 * BK * NQ];   // 16 KB: W1 rows for 16 chunks
    __shared__ float sB1[16 * BK];        // 2 KB
    const int t = threadIdx.x;
    const int cg = blockIdx.x;            // chunk group (16 chunks)
    const int mtile = blockIdx.y;
    const int k0 = cg * 16 * BK;          // 512 k's per group
    const int m0 = mtile * TMT;

    #pragma unroll
    for (int i = 0; i < 4; ++i)
        ((float4*)sW1)[t + i * 256] = ((const float4*)(W1 + (size_t)k0 * NQ))[t + i * 256];
    if (t < 128) ((float4*)sB1)[t] = ((const float4*)(b1 + k0))[t];
    __syncthreads();

    const int row = t >> 1;
    const int kb  = (t & 1) * 16;
    float qv[8];
    {
        const float4* xp = (const float4*)&x[(size_t)(m0 + row) * EMBED];
        float4 x0 = xp[0], x1 = xp[1];
        qv[0] = cosf(x0.x) * cosf(theta[0]); qv[1] = cosf(x0.y) * cosf(theta[1]);
        qv[2] = cosf(x0.z) * cosf(theta[2]); qv[3] = cosf(x0.w) * cosf(theta[3]);
        qv[4] = cosf(x1.x) * cosf(theta[4]); qv[5] = cosf(x1.y) * cosf(theta[5]);
        qv[6] = cosf(x1.z) * cosf(theta[6]); qv[7] = cosf(x1.w) * cosf(theta[7]);
    }

    const int x7 = row & 7;
    const int c0 = kb >> 3;               // 0 or 2
    char* gbase = g_A + ((size_t)(mtile * NCHUNK + cg * 16)) * 16384 + (uint32_t)row * 128;

    #pragma unroll 2
    for (int ch = 0; ch < 16; ++ch) {
        uint32_t hw[8], lw[8];
        #pragma unroll
        for (int p = 0; p < 8; ++p) {
            float v2[2];
            #pragma unroll
            for (int e = 0; e < 2; ++e) {
                int kk = ch * BK + kb + 2 * p + e;
                float4 w0 = ((const float4*)sW1)[kk * 2];
                float4 w1r = ((const float4*)sW1)[kk * 2 + 1];
                float a = sB1[kk];
                a = fmaf(qv[0], w0.x, a);  a = fmaf(qv[1], w0.y, a);
                a = fmaf(qv[2], w0.z, a);  a = fmaf(qv[3], w0.w, a);
                a = fmaf(qv[4], w1r.x, a); a = fmaf(qv[5], w1r.y, a);
                a = fmaf(qv[6], w1r.z, a); a = fmaf(qv[7], w1r.w, a);
                v2[e] = fmaxf(a, 0.0f);
            }
            split2(v2[0], v2[1], hw[p], lw[p]);
        }
        char* g = gbase + (size_t)ch * 16384;
        *(uint4*)(g + (uint32_t)(((c0 + 0) ^ x7) * 16)) = make_uint4(hw[0], hw[1], hw[2], hw[3]);
        *(uint4*)(g + (uint32_t)(((c0 + 1) ^ x7) * 16)) = make_uint4(hw[4], hw[5], hw[6], hw[7]);
        *(uint4*)(g + (uint32_t)(((c0 + 4) ^ x7) * 16)) = make_uint4(lw[0], lw[1], lw[2], lw[3]);
        *(uint4*)(g + (uint32_t)(((c0 + 5) ^ x7) * 16)) = make_uint4(lw[4], lw[5], lw[6], lw[7]);
    }
}

// ---------------- prep 2: B blocks = hi/lo bf16 of W2, tiled+swizzled (direct STG) ----------------
__global__ void __launch_bounds__(256) b_gen(const float* __restrict__ W2) {
    const int t = threadIdx.x;
    const int chunk = blockIdx.x, ntile = blockIdx.y;
    const int k0 = chunk * BK, n0 = ntile * 128;
    const int row = t >> 1;
    const int kb  = (t & 1) * 16;

    const float4* src = (const float4*)&W2[(size_t)(n0 + row) * FFN + k0 + kb];
    float v[16];
    #pragma unroll
    for (int i = 0; i < 4; ++i) {
        float4 f = src[i];
        v[4 * i] = f.x; v[4 * i + 1] = f.y; v[4 * i + 2] = f.z; v[4 * i + 3] = f.w;
    }
    uint32_t hw[8], lw[8];
    #pragma unroll
    for (int j = 0; j < 8; ++j) split2(v[2 * j], v[2 * j + 1], hw[j], lw[j]);

    const int x7 = row & 7;
    const int c0 = kb >> 3;
    char* g = g_B + ((size_t)(ntile * NCHUNK + chunk)) * 16384 + (uint32_t)row * 128;
    *(uint4*)(g + (uint32_t)(((c0 + 0) ^ x7) * 16)) = make_uint4(hw[0], hw[1], hw[2], hw[3]);
    *(uint4*)(g + (uint32_t)(((c0 + 1) ^ x7) * 16)) = make_uint4(hw[4], hw[5], hw[6], hw[7]);
    *(uint4*)(g + (uint32_t)(((c0 + 4) ^ x7) * 16)) = make_uint4(lw[0], lw[1], lw[2], lw[3]);
    *(uint4*)(g + (uint32_t)(((c0 + 5) ^ x7) * 16)) = make_uint4(lw[4], lw[5], lw[6], lw[7]);
}

// ---------------- GEMM path, templated on tile width (unchanged from round 12) ----------------
template<bool HALF>
__device__ __forceinline__ void gemm_path(
    uint32_t sb, const char* __restrict__ gA, const char* __restrict__ gB,
    int m0, int n0, const float* __restrict__ b2, float* __restrict__ out, int tid)
{
    constexpr int NJ = HALF ? 2 : 4;
    constexpr int NP = HALF ? 1 : 2;
    constexpr int NBU = HALF ? 2 : 4;

    const int wid  = tid >> 5;
    const int lane = tid & 31;
    const int mw  = wid & 1;
    const int nw  = wid >> 1;
    const int lr  = lane & 15;
    const int lkh = lane >> 4;
    const int lg  = lane >> 3;
    const int l7  = lane & 7;
    const int xa  = lr & 7;

    float acc[4][NJ][4];
    #pragma unroll
    for (int i = 0; i < 4; ++i)
        #pragma unroll
        for (int j = 0; j < NJ; ++j)
            #pragma unroll
            for (int r = 0; r < 4; ++r) acc[i][j][r] = 0.0f;

    auto cp_stage = [&](int chunk, uint32_t base) {
        const char* sa  = gA + (size_t)chunk * 16384;
        const char* sbg = gB + (size_t)chunk * 16384;
        #pragma unroll
        for (int i = 0; i < 4; ++i)
            cp_async16(base + A_OFF + (uint32_t)(tid + i * 256) * 16, sa + (size_t)(tid + i * 256) * 16);
        #pragma unroll
        for (int i = 0; i < NBU; ++i)
            cp_async16(base + B_OFF + (uint32_t)(tid + i * 256) * 16, sbg + (size_t)(tid + i * 256) * 16);
    };

    auto do_mma = [&](uint32_t base) {
        const uint32_t Ab = base + A_OFF;
        const uint32_t Bb = base + B_OFF;
        #pragma unroll
        for (int ks = 0; ks < 2; ++ks) {
            uint32_t ah[4][4], al[4][4], bh[NP][4], bl[NP][4];
            #pragma unroll
            for (int i = 0; i < 4; ++i) {
                uint32_t row = (uint32_t)(mw * 64 + i * 16 + lr) * 128;
                ldm_x4(ah[i], Ab + row + (uint32_t)(((2 * ks + lkh) ^ xa) * 16));
            }
            #pragma unroll
            for (int p = 0; p < NP; ++p) {
                uint32_t row = HALF
                    ? (uint32_t)(nw * 16 + (lg >> 1) * 8 + l7) * 128
                    : (uint32_t)(nw * 32 + (2 * p + (lg >> 1)) * 8 + l7) * 128;
                ldm_x4(bh[p], Bb + row + (uint32_t)(((2 * ks + (lg & 1)) ^ l7) * 16));
            }
            #pragma unroll
            for (int i = 0; i < 4; ++i)
                #pragma unroll
                for (int j = 0; j < NJ; ++j)
                    mma16816(acc[i][j], ah[i], bh[j >> 1][2 * (j & 1)], bh[j >> 1][2 * (j & 1) + 1]);
            #pragma unroll
            for (int p = 0; p < NP; ++p) {
                uint32_t row = HALF
                    ? (uint32_t)(nw * 16 + (lg >> 1) * 8 + l7) * 128
                    : (uint32_t)(nw * 32 + (2 * p + (lg >> 1)) * 8 + l7) * 128;
                ldm_x4(bl[p], Bb + row + (uint32_t)(((2 * ks + (lg & 1) + 4) ^ l7) * 16));
            }
            #pragma unroll
            for (int i = 0; i < 4; ++i)
                #pragma unroll
                for (int j = 0; j < NJ; ++j)
                    mma16816(acc[i][j], ah[i], bl[j >> 1][2 * (j & 1)], bl[j >> 1][2 * (j & 1) + 1]);
            #pragma unroll
            for (int i = 0; i < 4; ++i) {
                uint32_t row = (uint32_t)(mw * 64 + i * 16 + lr) * 128;
                ldm_x4(al[i], Ab + row + (uint32_t)(((2 * ks + lkh + 4) ^ xa) * 16));
            }
            #pragma unroll
            for (int i = 0; i < 4; ++i)
                #pragma unroll
                for (int j = 0; j < NJ; ++j)
                    mma16816(acc[i][j], al[i], bh[j >> 1][2 * (j & 1)], bh[j >> 1][2 * (j & 1) + 1]);
        }
    };

    cp_stage(0, sb + 0 * STAGE); cp_commit();
    cp_stage(1, sb + 1 * STAGE); cp_commit();
    cp_wait1();
    __syncthreads();

    for (int cb = 0; cb < NCHUNK - 2; cb += 3) {
        #pragma unroll
        for (int j = 0; j < 3; ++j) {
            cp_stage(cb + j + 2, sb + ((j + 2) % 3) * STAGE);
            cp_commit();
            do_mma(sb + j * STAGE);
            cp_wait1();
            __syncthreads();
        }
    }
    do_mma(sb + 0 * STAGE);
    cp_wait0();
    __syncthreads();
    do_mma(sb + 1 * STAGE);

    const int rw = lane >> 2;
    const int cw = 2 * (lane & 3);
    #pragma unroll
    for (int j = 0; j < NJ; ++j) {
        int colg = n0 + nw * (HALF ? 16 : 32) + j * 8 + cw;
        float2 bv = *(const float2*)&b2[colg];
        #pragma unroll
        for (int i = 0; i < 4; ++i) {
            int rowg = m0 + mw * 64 + i * 16 + rw;
            float2 o0 = make_float2(acc[i][j][0] + bv.x, acc[i][j][1] + bv.y);
            float2 o1 = make_float2(acc[i][j][2] + bv.x, acc[i][j][3] + bv.y);
            *(float2*)&out[(size_t)rowg * EMBED + colg] = o0;
            *(float2*)&out[(size_t)(rowg + 8) * EMBED + colg] = o1;
        }
    }
}

__global__ void __launch_bounds__(NTHREADS, 2)
ffq_mm(const float* __restrict__ b2, float* __restrict__ out)
{
    extern __shared__ __align__(1024) char smem[];
    const uint32_t sb = smem_u32(smem);
    const int tid = threadIdx.x;
    const int flat = blockIdx.x;

    if (flat < NFULL) {
        const int mtile = flat >> 3;
        const int n0 = (flat & 7) * 128;
        const char* gA = g_A + (size_t)mtile * NCHUNK * 16384;
        const char* gB = g_B + (size_t)(n0 >> 7) * NCHUNK * 16384;
        gemm_path<false>(sb, gA, gB, mtile * TMT, n0, b2, out, tid);
    } else {
        const int r = flat - NFULL;
        const int mtile = FULL_MT + (r >> 4);
        const int nh = r & 15;
        const int n0 = nh * 64;
        const char* gA = g_A + (size_t)mtile * NCHUNK * 16384;
        const char* gB = g_B + (size_t)(nh >> 1) * NCHUNK * 16384 + (size_t)(nh & 1) * 64 * 128;
        gemm_path<true>(sb, gA, gB, mtile * TMT, n0, b2, out, tid);
    }
}

extern "C" void kernel_launch(void* const* d_in, const int* in_sizes, int n_in,
                              void* d_out, int out_size) {
    const float* x     = (const float*)d_in[0];
    const float* theta = (const float*)d_in[1];
    const float* W1    = (const float*)d_in[2];
    const float* b1    = (const float*)d_in[3];
    const float* W2    = (const float*)d_in[4];
    const float* b2    = (const float*)d_in[5];
    float* out = (float*)d_out;

    cudaFuncSetAttribute(ffq_mm, cudaFuncAttributeMaxDynamicSharedMemorySize, SMEM_TOTAL);

    b_gen<<<dim3(NCHUNK, NNTILE), 256>>>(W2);
    a_gen<<<dim3(8, NMTILE), 256>>>(x, theta, W1, b1);
    ffq_mm<<<GRID_MM, NTHREADS, SMEM_TOTAL>>>(b2, out);
}

// round 16
// speedup vs baseline: 4.2999x; 1.4863x over previous
#include <cuda_runtime.h>
#include <cuda_fp16.h>
#include <cstdint>

#define M_TOK  16384
#define EMBED  1024
#define FFN    4096
#define NQ     8

#define TMT    128
#define BK     32
#define NCHUNK (FFN / BK)      // 128
#define NMTILE (M_TOK / TMT)   // 128
#define NNTILE (EMBED / 128)   // 8
#define NTHREADS 256

#define FULL_MT   111
#define NFULL     (FULL_MT * NNTILE)        // 888 = 3 full waves at 2 CTA/SM
#define NHALF     ((NMTILE - FULL_MT) * 16) // 272 half tiles (128x64)
#define GRID_MM   (NFULL + NHALF)           // 1160

// A block: 8KB = 64 rows x 128B. smem-row r, unit u(16B=8 fp16):
//   m = r + (u>=4)*64, k-unit = u&3 (8 k's each), phys unit = u ^ (r&7).
// B block: 16KB = 128 n-rows x 128B. units 0-3 = bh(k0..31), 4-7 = bl, phys = u ^ (row&7).
#define A_BYTES 8192
#define B_BYTES 16384
#define A_OFF  0
#define B_OFF  8192
#define STAGE  24576
#define SMEM_TOTAL (3 * STAGE)

__device__ char g_A[(size_t)NMTILE * NCHUNK * A_BYTES];   // 134 MB, single fp16
__device__ char g_B[(size_t)NNTILE * NCHUNK * B_BYTES];   // 16 MB, fp16 hi/lo

// ---------------- helpers ----------------
__device__ __forceinline__ uint32_t smem_u32(const void* p) {
    uint32_t a;
    asm("{ .reg .u64 t; cvta.to.shared.u64 t, %1; cvt.u32.u64 %0, t; }" : "=r"(a) : "l"(p));
    return a;
}
__device__ __forceinline__ void cp_async16(uint32_t dst, const void* src) {
    asm volatile("cp.async.cg.shared.global [%0], [%1], 16;" :: "r"(dst), "l"(src) : "memory");
}
__device__ __forceinline__ void cp_commit() {
    asm volatile("cp.async.commit_group;" ::: "memory");
}
__device__ __forceinline__ void cp_wait1() {
    asm volatile("cp.async.wait_group 1;" ::: "memory");
}
__device__ __forceinline__ void cp_wait0() {
    asm volatile("cp.async.wait_group 0;" ::: "memory");
}
__device__ __forceinline__ void ldm_x4(uint32_t* r, uint32_t addr) {
    asm volatile("ldmatrix.sync.aligned.m8n8.x4.shared.b16 {%0,%1,%2,%3}, [%4];"
                 : "=r"(r[0]), "=r"(r[1]), "=r"(r[2]), "=r"(r[3]) : "r"(addr));
}
__device__ __forceinline__ void mma16816(float* d, const uint32_t* a, uint32_t b0, uint32_t b1) {
    asm volatile("mma.sync.aligned.m16n8k16.row.col.f32.f16.f16.f32 "
                 "{%0,%1,%2,%3}, {%4,%5,%6,%7}, {%8,%9}, {%0,%1,%2,%3};"
                 : "+f"(d[0]), "+f"(d[1]), "+f"(d[2]), "+f"(d[3])
                 : "r"(a[0]), "r"(a[1]), "r"(a[2]), "r"(a[3]), "r"(b0), "r"(b1));
}
__device__ __forceinline__ uint32_t pack_h2(float v0, float v1) {
    __half2 h = __float22half2_rn(make_float2(v0, v1));
    return *(uint32_t*)&h;
}
__device__ __forceinline__ void split2h(float v0, float v1, uint32_t& h, uint32_t& l) {
    __half2 hp = __float22half2_rn(make_float2(v0, v1));
    float2 hf = __half22float2(hp);
    __half2 lp = __float22half2_rn(make_float2(v0 - hf.x, v1 - hf.y));
    h = *(uint32_t*)&hp;
    l = *(uint32_t*)&lp;
}

// ---------------- prep 1: A blocks = fp16 of relu(q@W1^T + b1), amortized over 16 chunks ----------------
// grid: (8 chunk-groups, 128 mtiles). thread: m = t&127, kb = (t>>7)*16.
__global__ void __launch_bounds__(256) a_gen(const float* __restrict__ x, const float* __restrict__ theta,
                                             const float* __restrict__ W1, const float* __restrict__ b1) {
    __shared__ float sW1[16 * BK * NQ];   // 16 KB
    __shared__ float sB1[16 * BK];        // 2 KB
    const int t = threadIdx.x;
    const int cg = blockIdx.x;
    const int mtile = blockIdx.y;
    const int k0 = cg * 16 * BK;
    const int m0 = mtile * TMT;

    #pragma unroll
    for (int i = 0; i < 4; ++i)
        ((float4*)sW1)[t + i * 256] = ((const float4*)(W1 + (size_t)k0 * NQ))[t + i * 256];
    if (t < 128) ((float4*)sB1)[t] = ((const float4*)(b1 + k0))[t];
    __syncthreads();

    const int m  = t & 127;
    const int kb = (t >> 7) * 16;
    float qv[8];
    {
        const float4* xp = (const float4*)&x[(size_t)(m0 + m) * EMBED];
        float4 x0 = xp[0], x1 = xp[1];
        qv[0] = cosf(x0.x) * cosf(theta[0]); qv[1] = cosf(x0.y) * cosf(theta[1]);
        qv[2] = cosf(x0.z) * cosf(theta[2]); qv[3] = cosf(x0.w) * cosf(theta[3]);
        qv[4] = cosf(x1.x) * cosf(theta[4]); qv[5] = cosf(x1.y) * cosf(theta[5]);
        qv[6] = cosf(x1.z) * cosf(theta[6]); qv[7] = cosf(x1.w) * cosf(theta[7]);
    }

    const int r  = m & 63;
    const int u0 = (m >> 6) * 4 + (kb >> 3);    // {0,2} or {4,6}
    const int x7 = r & 7;
    char* gbase = g_A + ((size_t)(mtile * NCHUNK + cg * 16)) * A_BYTES + (uint32_t)r * 128;

    #pragma unroll 2
    for (int ch = 0; ch < 16; ++ch) {
        uint32_t w[8];
        #pragma unroll
        for (int p = 0; p < 8; ++p) {
            float v2[2];
            #pragma unroll
            for (int e = 0; e < 2; ++e) {
                int kk = ch * BK + kb + 2 * p + e;
                float4 w0 = ((const float4*)sW1)[kk * 2];
                float4 w1r = ((const float4*)sW1)[kk * 2 + 1];
                float a = sB1[kk];
                a = fmaf(qv[0], w0.x, a);  a = fmaf(qv[1], w0.y, a);
                a = fmaf(qv[2], w0.z, a);  a = fmaf(qv[3], w0.w, a);
                a = fmaf(qv[4], w1r.x, a); a = fmaf(qv[5], w1r.y, a);
                a = fmaf(qv[6], w1r.z, a); a = fmaf(qv[7], w1r.w, a);
                v2[e] = fmaxf(a, 0.0f);
            }
            w[p] = pack_h2(v2[0], v2[1]);
        }
        char* g = gbase + (size_t)ch * A_BYTES;
        *(uint4*)(g + (uint32_t)(((u0 + 0) ^ x7) * 16)) = make_uint4(w[0], w[1], w[2], w[3]);
        *(uint4*)(g + (uint32_t)(((u0 + 1) ^ x7) * 16)) = make_uint4(w[4], w[5], w[6], w[7]);
    }
}

// ---------------- prep 2: B blocks = fp16 hi/lo of W2 ----------------
__global__ void __launch_bounds__(256) b_gen(const float* __restrict__ W2) {
    const int t = threadIdx.x;
    const int chunk = blockIdx.x, ntile = blockIdx.y;
    const int k0 = chunk * BK, n0 = ntile * 128;
    const int row = t >> 1;
    const int kb  = (t & 1) * 16;

    const float4* src = (const float4*)&W2[(size_t)(n0 + row) * FFN + k0 + kb];
    float v[16];
    #pragma unroll
    for (int i = 0; i < 4; ++i) {
        float4 f = src[i];
        v[4 * i] = f.x; v[4 * i + 1] = f.y; v[4 * i + 2] = f.z; v[4 * i + 3] = f.w;
    }
    uint32_t hw[8], lw[8];
    #pragma unroll
    for (int j = 0; j < 8; ++j) split2h(v[2 * j], v[2 * j + 1], hw[j], lw[j]);

    const int x7 = row & 7;
    const int c0 = kb >> 3;
    char* g = g_B + ((size_t)(ntile * NCHUNK + chunk)) * B_BYTES + (uint32_t)row * 128;
    *(uint4*)(g + (uint32_t)(((c0 + 0) ^ x7) * 16)) = make_uint4(hw[0], hw[1], hw[2], hw[3]);
    *(uint4*)(g + (uint32_t)(((c0 + 1) ^ x7) * 16)) = make_uint4(hw[4], hw[5], hw[6], hw[7]);
    *(uint4*)(g + (uint32_t)(((c0 + 4) ^ x7) * 16)) = make_uint4(lw[0], lw[1], lw[2], lw[3]);
    *(uint4*)(g + (uint32_t)(((c0 + 5) ^ x7) * 16)) = make_uint4(lw[4], lw[5], lw[6], lw[7]);
}

// ---------------- GEMM path: 2-term fp16 (A single, B hi+lo) ----------------
template<bool HALF>
__device__ __forceinline__ void gemm_path(
    uint32_t sb, const char* __restrict__ gA, const char* __restrict__ gB,
    int m0, int n0, const float* __restrict__ b2, float* __restrict__ out, int tid)
{
    constexpr int NJ = HALF ? 2 : 4;
    constexpr int NP = HALF ? 1 : 2;
    constexpr int NBU = HALF ? 2 : 4;     // B cp units per thread
    constexpr int BLOAD = HALF ? 8192 : 16384;

    const int wid  = tid >> 5;
    const int lane = tid & 31;
    const int mw  = wid & 1;
    const int nw  = wid >> 1;
    const int lr  = lane & 15;
    const int lkh = lane >> 4;
    const int lg  = lane >> 3;
    const int l7  = lane & 7;
    const int mw4 = mw * 4;

    float acc[4][NJ][4];
    #pragma unroll
    for (int i = 0; i < 4; ++i)
        #pragma unroll
        for (int j = 0; j < NJ; ++j)
            #pragma unroll
            for (int r = 0; r < 4; ++r) acc[i][j][r] = 0.0f;

    auto cp_stage = [&](int chunk, uint32_t base) {
        const char* sa  = gA + (size_t)chunk * A_BYTES;
        const char* sbg = gB + (size_t)chunk * B_BYTES;
        #pragma unroll
        for (int i = 0; i < 2; ++i)
            cp_async16(base + A_OFF + (uint32_t)(tid + i * 256) * 16, sa + (size_t)(tid + i * 256) * 16);
        #pragma unroll
        for (int i = 0; i < NBU; ++i)
            cp_async16(base + B_OFF + (uint32_t)(tid + i * 256) * 16, sbg + (size_t)(tid + i * 256) * 16);
    };

    auto do_mma = [&](uint32_t base) {
        const uint32_t Ab = base + A_OFF;
        const uint32_t Bb = base + B_OFF;
        #pragma unroll
        for (int ks = 0; ks < 2; ++ks) {
            uint32_t a[4][4], bh[NP][4], bl[NP][4];
            #pragma unroll
            for (int i = 0; i < 4; ++i) {
                uint32_t r = (uint32_t)(i * 16 + lr);
                ldm_x4(a[i], Ab + r * 128 + (uint32_t)(((mw4 + 2 * ks + lkh) ^ (r & 7)) * 16));
            }
            #pragma unroll
            for (int p = 0; p < NP; ++p) {
                uint32_t row = HALF
                    ? (uint32_t)(nw * 16 + (lg >> 1) * 8 + l7) * 128
                    : (uint32_t)(nw * 32 + (2 * p + (lg >> 1)) * 8 + l7) * 128;
                ldm_x4(bh[p], Bb + row + (uint32_t)(((2 * ks + (lg & 1)) ^ l7) * 16));
            }
            #pragma unroll
            for (int i = 0; i < 4; ++i)
                #pragma unroll
                for (int j = 0; j < NJ; ++j)
                    mma16816(acc[i][j], a[i], bh[j >> 1][2 * (j & 1)], bh[j >> 1][2 * (j & 1) + 1]);
            #pragma unroll
            for (int p = 0; p < NP; ++p) {
                uint32_t row = HALF
                    ? (uint32_t)(nw * 16 + (lg >> 1) * 8 + l7) * 128
                    : (uint32_t)(nw * 32 + (2 * p + (lg >> 1)) * 8 + l7) * 128;
                ldm_x4(bl[p], Bb + row + (uint32_t)(((2 * ks + (lg & 1) + 4) ^ l7) * 16));
            }
            #pragma unroll
            for (int i = 0; i < 4; ++i)
                #pragma unroll
                for (int j = 0; j < NJ; ++j)
                    mma16816(acc[i][j], a[i], bl[j >> 1][2 * (j & 1)], bl[j >> 1][2 * (j & 1) + 1]);
        }
    };

    cp_stage(0, sb + 0 * STAGE); cp_commit();
    cp_stage(1, sb + 1 * STAGE); cp_commit();
    cp_wait1();
    __syncthreads();

    for (int cb = 0; cb < NCHUNK - 2; cb += 3) {
        #pragma unroll
        for (int j = 0; j < 3; ++j) {
            cp_stage(cb + j + 2, sb + ((j + 2) % 3) * STAGE);
            cp_commit();
            do_mma(sb + j * STAGE);
            cp_wait1();
            __syncthreads();
        }
    }
    do_mma(sb + 0 * STAGE);
    cp_wait0();
    __syncthreads();
    do_mma(sb + 1 * STAGE);

    const int rw = lane >> 2;
    const int cw = 2 * (lane & 3);
    #pragma unroll
    for (int j = 0; j < NJ; ++j) {
        int colg = n0 + nw * (HALF ? 16 : 32) + j * 8 + cw;
        float2 bv = *(const float2*)&b2[colg];
        #pragma unroll
        for (int i = 0; i < 4; ++i) {
            int rowg = m0 + mw * 64 + i * 16 + rw;
            float2 o0 = make_float2(acc[i][j][0] + bv.x, acc[i][j][1] + bv.y);
            float2 o1 = make_float2(acc[i][j][2] + bv.x, acc[i][j][3] + bv.y);
            *(float2*)&out[(size_t)rowg * EMBED + colg] = o0;
            *(float2*)&out[(size_t)(rowg + 8) * EMBED + colg] = o1;
        }
    }
}

__global__ void __launch_bounds__(NTHREADS, 2)
ffq_mm(const float* __restrict__ b2, float* __restrict__ out)
{
    extern __shared__ __align__(1024) char smem[];
    const uint32_t sb = smem_u32(smem);
    const int tid = threadIdx.x;
    const int flat = blockIdx.x;

    if (flat < NFULL) {
        const int mtile = flat >> 3;
        const int n0 = (flat & 7) * 128;
        const char* gA = g_A + (size_t)mtile * NCHUNK * A_BYTES;
        const char* gB = g_B + (size_t)(n0 >> 7) * NCHUNK * B_BYTES;
        gemm_path<false>(sb, gA, gB, mtile * TMT, n0, b2, out, tid);
    } else {
        const int r = flat - NFULL;
        const int mtile = FULL_MT + (r >> 4);
        const int nh = r & 15;
        const int n0 = nh * 64;
        const char* gA = g_A + (size_t)mtile * NCHUNK * A_BYTES;
        const char* gB = g_B + (size_t)(nh >> 1) * NCHUNK * B_BYTES + (size_t)(nh & 1) * 64 * 128;
        gemm_path<true>(sb, gA, gB, mtile * TMT, n0, b2, out, tid);
    }
}

extern "C" void kernel_launch(void* const* d_in, const int* in_sizes, int n_in,
                              void* d_out, int out_size) {
    const float* x     = (const float*)d_in[0];
    const float* theta = (const float*)d_in[1];
    const float* W1    = (const float*)d_in[2];
    const float* b1    = (const float*)d_in[3];
    const float* W2    = (const float*)d_in[4];
    const float* b2    = (const float*)d_in[5];
    float* out = (float*)d_out;

    cudaFuncSetAttribute(ffq_mm, cudaFuncAttributeMaxDynamicSharedMemorySize, SMEM_TOTAL);

    b_gen<<<dim3(NCHUNK, NNTILE), 256>>>(W2);
    a_gen<<<dim3(8, NMTILE), 256>>>(x, theta, W1, b1);
    ffq_mm<<<GRID_MM, NTHREADS, SMEM_TOTAL>>>(b2, out);
}